// round 1
// baseline (speedup 1.0000x reference)
#include <cuda_runtime.h>
#include <cuda_bf16.h>
#include <mma.h>
#include <cstdint>

using namespace nvcuda;

#define BATCH 2048
#define NIN   2048
#define NG    8192
#define NCOL  16384  // NG*2

// Scratch (static device globals -- allocation-free rule)
__device__ __nv_bfloat16 g_P[(size_t)NIN * NCOL];     // exp(c), 67 MB
__device__ __nv_bfloat16 g_xb[(size_t)BATCH * NIN];   // x in bf16, 8 MB
__device__ float g_spart[16 * NCOL];                  // partial column sums
__device__ float g_rs[NCOL];                          // 1/colsum
__device__ float g_coef[4 * NG];                      // alpha,beta,gamma,delta

// ---------------------------------------------------------------------------
// Kernel 1: x -> bf16
__global__ void k_xcvt(const float* __restrict__ x) {
    int i = blockIdx.x * 256 + threadIdx.x;
    g_xb[i] = __float2bfloat16(x[i]);
}

// ---------------------------------------------------------------------------
// Kernel 2: P = exp(c) (bf16) + partial column sums (fp32).
// grid (64, 16), block 256. Each thread: one column j, 128 rows.
__global__ void k_exp(const float* __restrict__ c) {
    int j = blockIdx.x * 256 + threadIdx.x;
    int i0 = blockIdx.y * 128;
    float s = 0.f;
#pragma unroll 4
    for (int ii = 0; ii < 128; ++ii) {
        size_t idx = (size_t)(i0 + ii) * NCOL + j;
        float e = __expf(c[idx]);
        g_P[idx] = __float2bfloat16(e);
        s += e;
    }
    g_spart[blockIdx.y * NCOL + j] = s;
}

// Kernel 3: reduce partials -> reciprocal column sums
__global__ void k_sred() {
    int j = blockIdx.x * 256 + threadIdx.x;
    float s = 0.f;
#pragma unroll
    for (int cK = 0; cK < 16; ++cK) s += g_spart[cK * NCOL + j];
    g_rs[j] = 1.f / s;
}

// ---------------------------------------------------------------------------
// Kernel 4: per-gate affine coefficients from softmax(w).
// gates are affine in (1, A, B, AB):
//  g0=0, g1=AB, g2=A-AB, g3=A, g4=B-AB, g5=B, g6=A+B-2AB, g7=A+B-AB,
//  g8=1-A-B+AB, g9=1-A-B+2AB, g10=1-B, g11=1-B+AB, g12=1-A, g13=1-A+AB,
//  g14=1-AB, g15=1
__global__ void k_coef(const float* __restrict__ w) {
    int g = blockIdx.x * 256 + threadIdx.x;
    if (g >= NG) return;
    float v[16];
    float m = -1e30f;
#pragma unroll
    for (int k = 0; k < 16; ++k) { v[k] = w[k * NG + g]; m = fmaxf(m, v[k]); }
    float sum = 0.f;
#pragma unroll
    for (int k = 0; k < 16; ++k) { v[k] = __expf(v[k] - m); sum += v[k]; }
    float inv = 1.f / sum;
#pragma unroll
    for (int k = 0; k < 16; ++k) v[k] *= inv;

    float al = v[8]+v[9]+v[10]+v[11]+v[12]+v[13]+v[14]+v[15];
    float be = v[2]+v[3]+v[6]+v[7] - v[8]-v[9]-v[12]-v[13];
    float ga = v[4]+v[5]+v[6]+v[7] - v[8]-v[9]-v[10]-v[11];
    float de = v[1]-v[2]-v[4]-2.f*v[6]-v[7]+v[8]+2.f*v[9]+v[11]+v[13]-v[14];
    g_coef[g]          = al;
    g_coef[NG + g]     = be;
    g_coef[2*NG + g]   = ga;
    g_coef[3*NG + g]   = de;
}

// ---------------------------------------------------------------------------
// Kernel 5: GEMM y = xb @ P (bf16 -> fp32) with fused gate epilogue.
// BM=128, BN=128, BK=64. 256 threads = 8 warps (2 in M x 4 in N),
// warp tile 64x32 = 4x2 wmma 16x16x16 fragments.
#define BM 128
#define BN 128
#define BK 64
#define LDA 72    // 144 B rows (16B multiple)
#define LDB 136   // 272 B rows (16B multiple)

__global__ __launch_bounds__(256) void k_gemm(float* __restrict__ out) {
    __shared__ __align__(16) unsigned char smraw[BM * LDA * 2 + BK * LDB * 2];
    __nv_bfloat16* As = (__nv_bfloat16*)smraw;
    __nv_bfloat16* Bs = (__nv_bfloat16*)(smraw + BM * LDA * 2);

    const int tid = threadIdx.x;
    const int bn = blockIdx.x, bm = blockIdx.y;
    const int w = tid >> 5, lane = tid & 31;
    const int wm = w >> 2, wn = w & 3;

    wmma::fragment<wmma::accumulator, 16, 16, 16, float> acc[4][2];
#pragma unroll
    for (int mi = 0; mi < 4; ++mi)
#pragma unroll
        for (int ni = 0; ni < 2; ++ni)
            wmma::fill_fragment(acc[mi][ni], 0.f);

    for (int k0 = 0; k0 < NIN; k0 += BK) {
        // A tile: 128 rows x 64 cols = 1024 x uint4 (8 bf16 each)
#pragma unroll
        for (int it = 0; it < 4; ++it) {
            int idx = tid + it * 256;
            int r = idx >> 3, cc = idx & 7;
            *(uint4*)(As + r * LDA + cc * 8) =
                *(const uint4*)(g_xb + (size_t)(bm * BM + r) * NIN + k0 + cc * 8);
        }
        // B tile: 64 rows x 128 cols = 1024 x uint4
#pragma unroll
        for (int it = 0; it < 4; ++it) {
            int idx = tid + it * 256;
            int r = idx >> 4, cc = idx & 15;
            *(uint4*)(Bs + r * LDB + cc * 8) =
                *(const uint4*)(g_P + (size_t)(k0 + r) * NCOL + bn * BN + cc * 8);
        }
        __syncthreads();

#pragma unroll
        for (int kk = 0; kk < BK / 16; ++kk) {
            wmma::fragment<wmma::matrix_a, 16, 16, 16, __nv_bfloat16, wmma::row_major> af[4];
            wmma::fragment<wmma::matrix_b, 16, 16, 16, __nv_bfloat16, wmma::row_major> bf[2];
#pragma unroll
            for (int mi = 0; mi < 4; ++mi)
                wmma::load_matrix_sync(af[mi], As + (wm * 64 + mi * 16) * LDA + kk * 16, LDA);
#pragma unroll
            for (int ni = 0; ni < 2; ++ni)
                wmma::load_matrix_sync(bf[ni], Bs + (kk * 16) * LDB + wn * 32 + ni * 16, LDB);
#pragma unroll
            for (int mi = 0; mi < 4; ++mi)
#pragma unroll
                for (int ni = 0; ni < 2; ++ni)
                    wmma::mma_sync(acc[mi][ni], af[mi], bf[ni], acc[mi][ni]);
        }
        __syncthreads();
    }

    // Fused epilogue: A = y[:,2g]/s, B = y[:,2g+1]/s, out = al + be*A + ga*B + de*A*B
    float* epi = ((float*)smraw) + w * 256;  // per-warp 16x16 scratch (1 KB)
#pragma unroll
    for (int mi = 0; mi < 4; ++mi) {
#pragma unroll
        for (int ni = 0; ni < 2; ++ni) {
            __syncwarp();
            wmma::store_matrix_sync(epi, acc[mi][ni], 16, wmma::mem_row_major);
            __syncwarp();
            int coln0 = bn * BN + wn * 32 + ni * 16;  // even
            int g0 = coln0 >> 1;
            int row0 = bm * BM + wm * 64 + mi * 16;
#pragma unroll
            for (int q = 0; q < 4; ++q) {
                int idx = lane + q * 32;     // 0..127
                int r = idx >> 3, p = idx & 7;
                float Av = epi[r * 16 + 2 * p]     * g_rs[coln0 + 2 * p];
                float Bv = epi[r * 16 + 2 * p + 1] * g_rs[coln0 + 2 * p + 1];
                int g = g0 + p;
                float al = g_coef[g];
                float be = g_coef[NG + g];
                float ga = g_coef[2 * NG + g];
                float de = g_coef[3 * NG + g];
                out[(size_t)(row0 + r) * NG + g] = al + be * Av + ga * Bv + de * Av * Bv;
            }
        }
    }
}

// ---------------------------------------------------------------------------
extern "C" void kernel_launch(void* const* d_in, const int* in_sizes, int n_in,
                              void* d_out, int out_size) {
    const float* x = (const float*)d_in[0];  // (2048, 2048)
    const float* w = (const float*)d_in[1];  // (16, 8192)
    const float* c = (const float*)d_in[2];  // (2048, 8192, 2)
    float* out = (float*)d_out;              // (2048, 8192)

    k_xcvt<<<(BATCH * NIN) / 256, 256>>>(x);
    k_coef<<<NG / 256, 256>>>(w);
    k_exp<<<dim3(NCOL / 256, 16), 256>>>(c);
    k_sred<<<NCOL / 256, 256>>>();
    k_gemm<<<dim3(NCOL / BN, BATCH / BM), 256>>>(out);
}